// round 1
// baseline (speedup 1.0000x reference)
#include <cuda_runtime.h>

// ---------------------------------------------------------------------------
// CrossModalAttention collapses analytically:
//   fa[b,s,:] is constant over s  =>  K_a, V_a constant over t
//   => scores[b,s,t] constant over t => softmax == uniform 1/S
//   => attn_out[b,s,:] == va[b,:]  where va = (acoustic@Wa+ba)@Wv + bv
//   => out = text@Wt + bt + va[b]   (one real GEMM)
// ---------------------------------------------------------------------------

#define BATCH 8
#define SEQ   2048
#define D     768
#define DAUD  16
#define M_TOT (BATCH * SEQ)   // 16384

__device__ float g_va[BATCH * D];

// ---------------------------------------------------------------------------
// Kernel A: va[b,:] = (acoustic[b,:] @ Wa + ba) @ Wv + bv       (tiny)
// 8 blocks x 768 threads.
// ---------------------------------------------------------------------------
__global__ void va_kernel(const float* __restrict__ ac,
                          const float* __restrict__ Wa,
                          const float* __restrict__ ba,
                          const float* __restrict__ Wv,
                          const float* __restrict__ bv) {
    __shared__ float fa[D];
    __shared__ float acs[DAUD];
    const int b = blockIdx.x;
    const int t = threadIdx.x;         // 0..767

    if (t < DAUD) acs[t] = ac[b * DAUD + t];
    __syncthreads();

    float v = ba[t];
#pragma unroll
    for (int k = 0; k < DAUD; k++)
        v += acs[k] * Wa[k * D + t];
    fa[t] = v;
    __syncthreads();

    float o = bv[t];
    for (int e = 0; e < D; e++)
        o += fa[e] * Wv[e * D + t];    // coalesced across t
    g_va[b * D + t] = o;
}

// ---------------------------------------------------------------------------
// Kernel B: out[m, n] = sum_k text[m,k]*Wt[k,n] + bt[n] + va[m/2048, n]
// Classic fp32 SGEMM: 128x128 block tile, BK=8, 256 threads, 8x8 microtile.
// M=16384, N=768, K=768 -> all tile-aligned, no bounds checks.
// ---------------------------------------------------------------------------
#define BM 128
#define BN 128
#define BK 8
#define TM 8
#define TN 8

__global__ __launch_bounds__(256, 2)
void gemm_epilogue_kernel(const float* __restrict__ A,   // [16384, 768]
                          const float* __restrict__ W,   // [768, 768]
                          const float* __restrict__ bias,// [768]
                          float* __restrict__ out) {     // [16384, 768]
    __shared__ float As[BK][BM];
    __shared__ float Bs[BK][BN];

    const int bn = blockIdx.x;         // 0..5
    const int bm = blockIdx.y;         // 0..127
    const int tid = threadIdx.x;
    const int tx = tid & 15;           // 0..15
    const int ty = tid >> 4;           // 0..15

    const float* Aptr = A + (bm * BM) * D;
    const float* Wptr = W + bn * BN;

    // A-tile load mapping: 128 rows x 8 cols = 256 float4
    const int arow = tid >> 1;               // 0..127
    const int acol = (tid & 1) * 4;          // 0 or 4
    // W-tile load mapping: 8 rows x 128 cols = 256 float4
    const int wrow = tid >> 5;               // 0..7
    const int wcol = (tid & 31) * 4;         // 0..124

    float acc[TM][TN] = {};
    float af[TM], bf[TN];

    for (int k0 = 0; k0 < D; k0 += BK) {
        float4 av = *(const float4*)(Aptr + arow * D + k0 + acol);
        As[acol + 0][arow] = av.x;
        As[acol + 1][arow] = av.y;
        As[acol + 2][arow] = av.z;
        As[acol + 3][arow] = av.w;
        *(float4*)&Bs[wrow][wcol] =
            *(const float4*)(Wptr + (k0 + wrow) * D + wcol);
        __syncthreads();

#pragma unroll
        for (int k = 0; k < BK; k++) {
#pragma unroll
            for (int i = 0; i < TM; i++) af[i] = As[k][ty * TM + i];
#pragma unroll
            for (int j = 0; j < TN; j++) bf[j] = Bs[k][tx * TN + j];
#pragma unroll
            for (int i = 0; i < TM; i++)
#pragma unroll
                for (int j = 0; j < TN; j++)
                    acc[i][j] += af[i] * bf[j];
        }
        __syncthreads();
    }

    // Epilogue: + bias + va[b].  All 128 rows of this block share one b.
    const int bidx = bm >> 4;                     // (bm*128)/2048
    const int col0 = bn * BN + tx * TN;
    const float* __restrict__ vap = g_va + bidx * D + col0;

    float addv[TN];
#pragma unroll
    for (int j = 0; j < TN; j++)
        addv[j] = bias[col0 + j] + vap[j];

#pragma unroll
    for (int i = 0; i < TM; i++) {
        const int row = bm * BM + ty * TM + i;
        float* op = out + row * D + col0;
        float4 o0, o1;
        o0.x = acc[i][0] + addv[0];
        o0.y = acc[i][1] + addv[1];
        o0.z = acc[i][2] + addv[2];
        o0.w = acc[i][3] + addv[3];
        o1.x = acc[i][4] + addv[4];
        o1.y = acc[i][5] + addv[5];
        o1.z = acc[i][6] + addv[6];
        o1.w = acc[i][7] + addv[7];
        *(float4*)(op + 0) = o0;
        *(float4*)(op + 4) = o1;
    }
}

// ---------------------------------------------------------------------------
// Launch.  Input order (setup_inputs): text, acoustic, Wt, bt, Wa, ba,
//                                      Wq, bq, Wk, bk, Wv, bv
// ---------------------------------------------------------------------------
extern "C" void kernel_launch(void* const* d_in, const int* in_sizes, int n_in,
                              void* d_out, int out_size) {
    const float* text = (const float*)d_in[0];
    const float* ac   = (const float*)d_in[1];
    const float* Wt   = (const float*)d_in[2];
    const float* bt   = (const float*)d_in[3];
    const float* Wa   = (const float*)d_in[4];
    const float* ba   = (const float*)d_in[5];
    const float* Wv   = (const float*)d_in[10];
    const float* bv   = (const float*)d_in[11];
    float* out = (float*)d_out;

    va_kernel<<<BATCH, D>>>(ac, Wa, ba, Wv, bv);

    dim3 grid(D / BN, M_TOT / BM);   // (6, 128)
    gemm_epilogue_kernel<<<grid, 256>>>(text, Wt, bt, out);
}

// round 3
// speedup vs baseline: 2.2935x; 2.2935x over previous
#include <cuda_runtime.h>
#include <cuda_bf16.h>
#include <cstdint>

// ===========================================================================
// CrossModalAttention collapses analytically:
//   fa[b,s,:] constant over s  =>  K_a, V_a constant over t
//   => scores constant over t => softmax uniform
//   => attn_out[b,s,:] == va[b,:],  va = (ac@Wa+ba)@Wv + bv
//   => out = text @ Wt + bt + va[b]         (one real GEMM)
// GEMM runs on tensor cores via bf16x3 fp32 emulation:
//   A*B ~= Ah*Bh + Ah*Bl + Al*Bh  (fp32 accum), error ~2^-18.
// Legacy path only (mma.sync + ldmatrix + cp.async): the harness toolchain
// assembles baseline compute_100 PTX, so tcgen05/TMEM is unavailable.
// ===========================================================================

#define BATCH 8
#define SEQ   2048
#define DM    768
#define DAUD  16
#define M_TOT (BATCH * SEQ)

__device__ float g_va[BATCH * DM];
__device__ __nv_bfloat16 g_Ah[M_TOT * DM];
__device__ __nv_bfloat16 g_Al[M_TOT * DM];
__device__ __nv_bfloat16 g_Bh[DM * DM];     // Wt transposed: [N, K]
__device__ __nv_bfloat16 g_Bl[DM * DM];

// ------------------------------ helpers ------------------------------------
__device__ __forceinline__ uint32_t smem_u32(const void* p) {
    uint32_t r;
    asm("{ .reg .u64 t; cvta.to.shared.u64 t, %1; cvt.u32.u64 %0, t; }"
        : "=r"(r) : "l"(p));
    return r;
}

#define SWZ(o) ((o) ^ (((o) >> 3) & 0x70))

__device__ __forceinline__ void cpasync16(uint32_t dst, const void* src) {
    asm volatile("cp.async.cg.shared.global [%0], [%1], 16;"
                 :: "r"(dst), "l"(src));
}

__device__ __forceinline__ void ldsm4(uint32_t* r, uint32_t addr) {
    asm volatile("ldmatrix.sync.aligned.m8n8.x4.shared.b16 {%0,%1,%2,%3}, [%4];"
                 : "=r"(r[0]), "=r"(r[1]), "=r"(r[2]), "=r"(r[3])
                 : "r"(addr));
}

__device__ __forceinline__ void mma16816(float* d,
                                         uint32_t a0, uint32_t a1,
                                         uint32_t a2, uint32_t a3,
                                         uint32_t b0, uint32_t b1) {
    asm volatile(
        "mma.sync.aligned.m16n8k16.row.col.f32.bf16.bf16.f32 "
        "{%0,%1,%2,%3}, {%4,%5,%6,%7}, {%8,%9}, {%0,%1,%2,%3};"
        : "+f"(d[0]), "+f"(d[1]), "+f"(d[2]), "+f"(d[3])
        : "r"(a0), "r"(a1), "r"(a2), "r"(a3), "r"(b0), "r"(b1));
}

// ---------------------------------------------------------------------------
// Prep A: fp32 text -> (bf16 hi, bf16 lo)
// ---------------------------------------------------------------------------
__global__ void split_text_kernel(const float* __restrict__ x) {
    size_t i = ((size_t)blockIdx.x * blockDim.x + threadIdx.x) * 4;
    float4 v = *(const float4*)(x + i);
    float f[4] = {v.x, v.y, v.z, v.w};
    __nv_bfloat16 h[4], l[4];
#pragma unroll
    for (int j = 0; j < 4; j++) {
        h[j] = __float2bfloat16(f[j]);
        l[j] = __float2bfloat16(f[j] - __bfloat162float(h[j]));
    }
    __nv_bfloat162* ph = (__nv_bfloat162*)(g_Ah + i);
    __nv_bfloat162* pl = (__nv_bfloat162*)(g_Al + i);
    ph[0] = __halves2bfloat162(h[0], h[1]);
    ph[1] = __halves2bfloat162(h[2], h[3]);
    pl[0] = __halves2bfloat162(l[0], l[1]);
    pl[1] = __halves2bfloat162(l[2], l[3]);
}

// ---------------------------------------------------------------------------
// Prep B: transpose + split Wt[K,N] -> g_Bh/g_Bl [N,K]
// ---------------------------------------------------------------------------
__global__ void wsplit_kernel(const float* __restrict__ W) {
    __shared__ float tile[32][33];
    int n0 = blockIdx.x * 32, k0 = blockIdx.y * 32;
    int tx = threadIdx.x, ty = threadIdx.y;
    for (int r = ty; r < 32; r += 8)
        tile[r][tx] = W[(size_t)(k0 + r) * DM + n0 + tx];
    __syncthreads();
    for (int r = ty; r < 32; r += 8) {
        float v = tile[tx][r];                 // = W[k0+tx][n0+r]
        __nv_bfloat16 h = __float2bfloat16(v);
        __nv_bfloat16 l = __float2bfloat16(v - __bfloat162float(h));
        g_Bh[(size_t)(n0 + r) * DM + k0 + tx] = h;
        g_Bl[(size_t)(n0 + r) * DM + k0 + tx] = l;
    }
}

// ---------------------------------------------------------------------------
// Prep C: va[b,:] = (acoustic[b,:] @ Wa + ba) @ Wv + bv
// ---------------------------------------------------------------------------
__global__ void va_kernel(const float* __restrict__ ac,
                          const float* __restrict__ Wa,
                          const float* __restrict__ ba,
                          const float* __restrict__ Wv,
                          const float* __restrict__ bv) {
    __shared__ float fa[DM];
    __shared__ float acs[DAUD];
    const int b = blockIdx.x;
    const int t = threadIdx.x;
    if (t < DAUD) acs[t] = ac[b * DAUD + t];
    __syncthreads();
    float v = ba[t];
#pragma unroll
    for (int k = 0; k < DAUD; k++) v += acs[k] * Wa[k * DM + t];
    fa[t] = v;
    __syncthreads();
    float o = bv[t];
    for (int e = 0; e < DM; e++) o += fa[e] * Wv[e * DM + t];
    g_va[b * DM + t] = o;
}

// ---------------------------------------------------------------------------
// GEMM: 128x128 CTA tile, 512 threads, KT=64 chunks, 2-stage cp.async ring.
// Warp grid 4x4, warp tile 32x32 (2 m-tiles x 4 n-tiles of m16n8k16).
// ---------------------------------------------------------------------------
#define KT      64
#define KSTEPS  4
#define NCHUNK  (DM / KT)                 // 12
#define TILEB   (128 * 128)               // 16 KB (128 rows x 128B)
#define STAGEB  (4 * TILEB)               // Ah, Al, Bh, Bl = 64 KB
#define SMEM_DYN (2 * STAGEB + 1024)

__device__ __forceinline__ void load_chunk(uint32_t stg,
                                           const __nv_bfloat16* const* g0,
                                           int k0, int tid) {
#pragma unroll
    for (int t = 0; t < 4; t++) {
        const uint32_t tb = stg + t * TILEB;
#pragma unroll
        for (int j = 0; j < 2; j++) {
            const int q = tid + j * 512;          // 0..1023
            const int row = q >> 3, cc = q & 7;
            cpasync16(tb + SWZ(row * 128 + cc * 16),
                      g0[t] + (size_t)row * DM + k0 + cc * 8);
        }
    }
    asm volatile("cp.async.commit_group;");
}

__global__ __launch_bounds__(512, 1)
void gemm_kernel(const float* __restrict__ bias, float* __restrict__ out) {
    extern __shared__ char dynsmem[];
    uint32_t base = smem_u32(dynsmem);
    base = (base + 1023u) & ~1023u;

    const int tid = threadIdx.x;
    const int wid = tid >> 5, lane = tid & 31;
    const int wm = wid >> 2, wn = wid & 3;
    const int bn = blockIdx.x, bm = blockIdx.y;

    const __nv_bfloat16* g0[4] = {
        g_Ah + (size_t)bm * 128 * DM,
        g_Al + (size_t)bm * 128 * DM,
        g_Bh + (size_t)bn * 128 * DM,
        g_Bl + (size_t)bn * 128 * DM };

    float acc[2][4][4] = {};

    // prologue: two chunks in flight
    load_chunk(base + 0 * STAGEB, g0, 0 * KT, tid);
    load_chunk(base + 1 * STAGEB, g0, 1 * KT, tid);

    for (int c = 0; c < NCHUNK; ++c) {
        asm volatile("cp.async.wait_group 1;");
        __syncthreads();

        const uint32_t stg = base + (c & 1) * STAGEB;
        const uint32_t Ah = stg,            Al = stg + TILEB;
        const uint32_t Bh = stg + 2*TILEB,  Bl = stg + 3*TILEB;

#pragma unroll
        for (int ks = 0; ks < KSTEPS; ks++) {
            uint32_t ah[2][4], al[2][4];
#pragma unroll
            for (int mt = 0; mt < 2; mt++) {
                const int row = wm * 32 + mt * 16 + (lane & 15);
                const int kb  = ks * 32 + (lane >> 4) * 16;
                const uint32_t off = SWZ(row * 128 + kb);
                ldsm4(ah[mt], Ah + off);
                ldsm4(al[mt], Al + off);
            }
#pragma unroll
            for (int p = 0; p < 2; p++) {
                uint32_t bh[4], bl[4];
                const int row = wn * 32 + p * 16 + (lane & 7) + ((lane >> 4) << 3);
                const int kb  = ks * 32 + ((lane >> 3) & 1) * 16;
                const uint32_t off = SWZ(row * 128 + kb);
                ldsm4(bh, Bh + off);
                ldsm4(bl, Bl + off);
#pragma unroll
                for (int mt = 0; mt < 2; mt++) {
                    float* d0 = acc[mt][2 * p];
                    float* d1 = acc[mt][2 * p + 1];
                    mma16816(d0, ah[mt][0], ah[mt][1], ah[mt][2], ah[mt][3], bh[0], bh[1]);
                    mma16816(d1, ah[mt][0], ah[mt][1], ah[mt][2], ah[mt][3], bh[2], bh[3]);
                    mma16816(d0, ah[mt][0], ah[mt][1], ah[mt][2], ah[mt][3], bl[0], bl[1]);
                    mma16816(d1, ah[mt][0], ah[mt][1], ah[mt][2], ah[mt][3], bl[2], bl[3]);
                    mma16816(d0, al[mt][0], al[mt][1], al[mt][2], al[mt][3], bh[0], bh[1]);
                    mma16816(d1, al[mt][0], al[mt][1], al[mt][2], al[mt][3], bh[2], bh[3]);
                }
            }
        }
        __syncthreads();
        if (c + 2 < NCHUNK)
            load_chunk(stg, g0, (c + 2) * KT, tid);
        else
            asm volatile("cp.async.commit_group;");   // keep group count in step
    }

    // Epilogue: out = acc + bias + va[b]
    const int bidx = bm >> 4;                   // (bm*128)/2048
#pragma unroll
    for (int mt = 0; mt < 2; mt++) {
        const int r0 = bm * 128 + wm * 32 + mt * 16 + (lane >> 2);
#pragma unroll
        for (int nt = 0; nt < 4; nt++) {
            const int col = bn * 128 + wn * 32 + nt * 8 + (lane & 3) * 2;
            const float bv0 = bias[col]     + g_va[bidx * DM + col];
            const float bv1 = bias[col + 1] + g_va[bidx * DM + col + 1];
            float2 v0, v1;
            v0.x = acc[mt][nt][0] + bv0;  v0.y = acc[mt][nt][1] + bv1;
            v1.x = acc[mt][nt][2] + bv0;  v1.y = acc[mt][nt][3] + bv1;
            *(float2*)(out + (size_t)r0 * DM + col)       = v0;
            *(float2*)(out + (size_t)(r0 + 8) * DM + col) = v1;
        }
    }
}

// ---------------------------------------------------------------------------
// Launch. Input order: text, acoustic, Wt, bt, Wa, ba, Wq,bq, Wk,bk, Wv,bv
// ---------------------------------------------------------------------------
extern "C" void kernel_launch(void* const* d_in, const int* in_sizes, int n_in,
                              void* d_out, int out_size) {
    const float* text = (const float*)d_in[0];
    const float* ac   = (const float*)d_in[1];
    const float* Wt   = (const float*)d_in[2];
    const float* bt   = (const float*)d_in[3];
    const float* Wa   = (const float*)d_in[4];
    const float* ba   = (const float*)d_in[5];
    const float* Wv   = (const float*)d_in[10];
    const float* bv   = (const float*)d_in[11];
    float* out = (float*)d_out;

    cudaFuncSetAttribute(gemm_kernel,
                         cudaFuncAttributeMaxDynamicSharedMemorySize, SMEM_DYN);

    split_text_kernel<<<(M_TOT * DM) / 4 / 256, 256>>>(text);
    wsplit_kernel<<<dim3(DM / 32, DM / 32), dim3(32, 8)>>>(Wt);
    va_kernel<<<BATCH, DM>>>(ac, Wa, ba, Wv, bv);

    gemm_kernel<<<dim3(DM / 128, M_TOT / 128), 512, SMEM_DYN>>>(bt, out);
}

// round 4
// speedup vs baseline: 2.5514x; 1.1124x over previous
#include <cuda_runtime.h>
#include <cuda_bf16.h>
#include <cstdint>

// ===========================================================================
// CrossModalAttention collapses analytically:
//   fa[b,s,:] constant over s => K_a, V_a constant over t
//   => softmax uniform => attn_out[b,s,:] == va[b,:]
//   => out = text @ Wt + bt + va[b]      (one real GEMM)
// GEMM on tensor cores via bf16x3 fp32 emulation (Ah*Bh + Ah*Bl + Al*Bh).
// Legacy mma.sync path (toolchain assembles baseline compute_100 PTX only).
// Round 4: warp tile 64x32 (CTA 256x128) -> 128 B LDS per MMA, longer MMA
// chains, fewer tensor bubbles.
// ===========================================================================

#define BATCH 8
#define SEQ   2048
#define DM    768
#define DAUD  16
#define M_TOT (BATCH * SEQ)

__device__ float g_va[BATCH * DM];
__device__ __nv_bfloat16 g_Ah[M_TOT * DM];
__device__ __nv_bfloat16 g_Al[M_TOT * DM];
__device__ __nv_bfloat16 g_Bh[DM * DM];     // Wt transposed: [N, K]
__device__ __nv_bfloat16 g_Bl[DM * DM];

// ------------------------------ helpers ------------------------------------
__device__ __forceinline__ uint32_t smem_u32(const void* p) {
    uint32_t r;
    asm("{ .reg .u64 t; cvta.to.shared.u64 t, %1; cvt.u32.u64 %0, t; }"
        : "=r"(r) : "l"(p));
    return r;
}

#define SWZ(o) ((o) ^ (((o) >> 3) & 0x70))

__device__ __forceinline__ void cpasync16(uint32_t dst, const void* src) {
    asm volatile("cp.async.cg.shared.global [%0], [%1], 16;"
                 :: "r"(dst), "l"(src));
}

__device__ __forceinline__ void ldsm4(uint32_t* r, uint32_t addr) {
    asm volatile("ldmatrix.sync.aligned.m8n8.x4.shared.b16 {%0,%1,%2,%3}, [%4];"
                 : "=r"(r[0]), "=r"(r[1]), "=r"(r[2]), "=r"(r[3])
                 : "r"(addr));
}

__device__ __forceinline__ void mma16816(float* d,
                                         const uint32_t* a,
                                         uint32_t b0, uint32_t b1) {
    asm volatile(
        "mma.sync.aligned.m16n8k16.row.col.f32.bf16.bf16.f32 "
        "{%0,%1,%2,%3}, {%4,%5,%6,%7}, {%8,%9}, {%0,%1,%2,%3};"
        : "+f"(d[0]), "+f"(d[1]), "+f"(d[2]), "+f"(d[3])
        : "r"(a[0]), "r"(a[1]), "r"(a[2]), "r"(a[3]), "r"(b0), "r"(b1));
}

// ---------------------------------------------------------------------------
// Prep A: fp32 text -> (bf16 hi, bf16 lo), 8 elems/thread, 16B stores.
// ---------------------------------------------------------------------------
__global__ void split_text_kernel(const float* __restrict__ x) {
    size_t i = ((size_t)blockIdx.x * blockDim.x + threadIdx.x) * 8;
    float4 v0 = *(const float4*)(x + i);
    float4 v1 = *(const float4*)(x + i + 4);
    float f[8] = {v0.x, v0.y, v0.z, v0.w, v1.x, v1.y, v1.z, v1.w};
    __nv_bfloat162 h[4], l[4];
#pragma unroll
    for (int j = 0; j < 4; j++) {
        __nv_bfloat16 h0 = __float2bfloat16(f[2*j]);
        __nv_bfloat16 h1 = __float2bfloat16(f[2*j+1]);
        __nv_bfloat16 l0 = __float2bfloat16(f[2*j]   - __bfloat162float(h0));
        __nv_bfloat16 l1 = __float2bfloat16(f[2*j+1] - __bfloat162float(h1));
        h[j] = __halves2bfloat162(h0, h1);
        l[j] = __halves2bfloat162(l0, l1);
    }
    *(uint4*)(g_Ah + i) = *(const uint4*)h;
    *(uint4*)(g_Al + i) = *(const uint4*)l;
}

// ---------------------------------------------------------------------------
// Prep B: transpose + split Wt[K,N] -> g_Bh/g_Bl [N,K]
// ---------------------------------------------------------------------------
__global__ void wsplit_kernel(const float* __restrict__ W) {
    __shared__ float tile[32][33];
    int n0 = blockIdx.x * 32, k0 = blockIdx.y * 32;
    int tx = threadIdx.x, ty = threadIdx.y;
    for (int r = ty; r < 32; r += 8)
        tile[r][tx] = W[(size_t)(k0 + r) * DM + n0 + tx];
    __syncthreads();
    for (int r = ty; r < 32; r += 8) {
        float v = tile[tx][r];                 // = W[k0+tx][n0+r]
        __nv_bfloat16 h = __float2bfloat16(v);
        __nv_bfloat16 l = __float2bfloat16(v - __bfloat162float(h));
        g_Bh[(size_t)(n0 + r) * DM + k0 + tx] = h;
        g_Bl[(size_t)(n0 + r) * DM + k0 + tx] = l;
    }
}

// ---------------------------------------------------------------------------
// Prep C: va[b,:] = (acoustic[b,:] @ Wa + ba) @ Wv + bv
// ---------------------------------------------------------------------------
__global__ void va_kernel(const float* __restrict__ ac,
                          const float* __restrict__ Wa,
                          const float* __restrict__ ba,
                          const float* __restrict__ Wv,
                          const float* __restrict__ bv) {
    __shared__ float fa[DM];
    __shared__ float acs[DAUD];
    const int b = blockIdx.x;
    const int t = threadIdx.x;
    if (t < DAUD) acs[t] = ac[b * DAUD + t];
    __syncthreads();
    float v = ba[t];
#pragma unroll
    for (int k = 0; k < DAUD; k++) v += acs[k] * Wa[k * DM + t];
    fa[t] = v;
    __syncthreads();
    float o = bv[t];
    for (int e = 0; e < DM; e++) o += fa[e] * Wv[e * DM + t];
    g_va[b * DM + t] = o;
}

// ---------------------------------------------------------------------------
// GEMM: CTA tile 256x128, 512 threads (16 warps, 4x4), warp tile 64x32.
// KT=64 chunks, 2-stage cp.async ring, SW128 smem.
// ---------------------------------------------------------------------------
#define BM      256
#define BN      128
#define KT      64
#define KSTEPS  4
#define NCHUNK  (DM / KT)                 // 12
#define TILE_A  (BM * 128)                // 32 KB (256 rows x 128B)
#define TILE_B  (BN * 128)                // 16 KB
#define STAGEB  (2 * TILE_A + 2 * TILE_B) // 96 KB
#define SMEM_DYN (2 * STAGEB + 1024)

__device__ __forceinline__ void load_chunk(uint32_t stg,
                                           const __nv_bfloat16* const* g0,
                                           int k0, int tid) {
    // A tiles: 2048 x 16B each, 4 iters/thread
#pragma unroll
    for (int t = 0; t < 2; t++) {
        const uint32_t tb = stg + t * TILE_A;
#pragma unroll
        for (int j = 0; j < 4; j++) {
            const int q = tid + j * 512;          // 0..2047
            const int row = q >> 3, cc = q & 7;
            cpasync16(tb + SWZ(row * 128 + cc * 16),
                      g0[t] + (size_t)row * DM + k0 + cc * 8);
        }
    }
    // B tiles: 1024 x 16B each, 2 iters/thread
#pragma unroll
    for (int t = 0; t < 2; t++) {
        const uint32_t tb = stg + 2 * TILE_A + t * TILE_B;
#pragma unroll
        for (int j = 0; j < 2; j++) {
            const int q = tid + j * 512;          // 0..1023
            const int row = q >> 3, cc = q & 7;
            cpasync16(tb + SWZ(row * 128 + cc * 16),
                      g0[2 + t] + (size_t)row * DM + k0 + cc * 8);
        }
    }
    asm volatile("cp.async.commit_group;");
}

__global__ __launch_bounds__(512, 1)
void gemm_kernel(const float* __restrict__ bias, float* __restrict__ out) {
    extern __shared__ char dynsmem[];
    uint32_t base = smem_u32(dynsmem);
    base = (base + 1023u) & ~1023u;

    const int tid = threadIdx.x;
    const int wid = tid >> 5, lane = tid & 31;
    const int wm = wid >> 2, wn = wid & 3;   // 4x4 warp grid
    const int bn = blockIdx.x, bm = blockIdx.y;

    const __nv_bfloat16* g0[4] = {
        g_Ah + (size_t)bm * BM * DM,
        g_Al + (size_t)bm * BM * DM,
        g_Bh + (size_t)bn * BN * DM,
        g_Bl + (size_t)bn * BN * DM };

    float acc[4][4][4] = {};

    load_chunk(base + 0 * STAGEB, g0, 0 * KT, tid);
    load_chunk(base + 1 * STAGEB, g0, 1 * KT, tid);

    for (int c = 0; c < NCHUNK; ++c) {
        asm volatile("cp.async.wait_group 1;");
        __syncthreads();

        const uint32_t stg = base + (c & 1) * STAGEB;
        const uint32_t Ah = stg,                 Al = stg + TILE_A;
        const uint32_t Bh = stg + 2 * TILE_A,    Bl = Bh + TILE_B;

#pragma unroll
        for (int ks = 0; ks < KSTEPS; ks++) {
            uint32_t ah[4][4], al[4][4];
            const int akb = ks * 32 + (lane >> 4) * 16;
#pragma unroll
            for (int mt = 0; mt < 4; mt++) {
                const int row = wm * 64 + mt * 16 + (lane & 15);
                const uint32_t off = SWZ(row * 128 + akb);
                ldsm4(ah[mt], Ah + off);
                ldsm4(al[mt], Al + off);
            }
            const int brow_base = wn * 32 + (lane & 7) + ((lane >> 4) << 3);
            const int bkb = ks * 32 + ((lane >> 3) & 1) * 16;
#pragma unroll
            for (int p = 0; p < 2; p++) {
                uint32_t bh[4], bl[4];
                const uint32_t off = SWZ((brow_base + p * 16) * 128 + bkb);
                ldsm4(bh, Bh + off);
                ldsm4(bl, Bl + off);
#pragma unroll
                for (int mt = 0; mt < 4; mt++) {
                    float* d0 = acc[mt][2 * p];
                    float* d1 = acc[mt][2 * p + 1];
                    mma16816(d0, ah[mt], bh[0], bh[1]);
                    mma16816(d1, ah[mt], bh[2], bh[3]);
                    mma16816(d0, ah[mt], bl[0], bl[1]);
                    mma16816(d1, ah[mt], bl[2], bl[3]);
                    mma16816(d0, al[mt], bh[0], bh[1]);
                    mma16816(d1, al[mt], bh[2], bh[3]);
                }
            }
        }
        __syncthreads();
        if (c + 2 < NCHUNK)
            load_chunk(stg, g0, (c + 2) * KT, tid);
        else
            asm volatile("cp.async.commit_group;");   // keep group count in step
    }

    // Epilogue: out = acc + bias + va[b].  BM=256 stays within one batch
    // (2048 % 256 == 0) -> bidx = bm >> 3.
    const int bidx = bm >> 3;
#pragma unroll
    for (int mt = 0; mt < 4; mt++) {
        const int r0 = bm * BM + wm * 64 + mt * 16 + (lane >> 2);
#pragma unroll
        for (int nt = 0; nt < 4; nt++) {
            const int col = bn * BN + wn * 32 + nt * 8 + (lane & 3) * 2;
            const float bv0 = bias[col]     + g_va[bidx * DM + col];
            const float bv1 = bias[col + 1] + g_va[bidx * DM + col + 1];
            float2 v0, v1;
            v0.x = acc[mt][nt][0] + bv0;  v0.y = acc[mt][nt][1] + bv1;
            v1.x = acc[mt][nt][2] + bv0;  v1.y = acc[mt][nt][3] + bv1;
            *(float2*)(out + (size_t)r0 * DM + col)       = v0;
            *(float2*)(out + (size_t)(r0 + 8) * DM + col) = v1;
        }
    }
}

// ---------------------------------------------------------------------------
// Launch. Input order: text, acoustic, Wt, bt, Wa, ba, Wq,bq, Wk,bk, Wv,bv
// ---------------------------------------------------------------------------
extern "C" void kernel_launch(void* const* d_in, const int* in_sizes, int n_in,
                              void* d_out, int out_size) {
    const float* text = (const float*)d_in[0];
    const float* ac   = (const float*)d_in[1];
    const float* Wt   = (const float*)d_in[2];
    const float* bt   = (const float*)d_in[3];
    const float* Wa   = (const float*)d_in[4];
    const float* ba   = (const float*)d_in[5];
    const float* Wv   = (const float*)d_in[10];
    const float* bv   = (const float*)d_in[11];
    float* out = (float*)d_out;

    cudaFuncSetAttribute(gemm_kernel,
                         cudaFuncAttributeMaxDynamicSharedMemorySize, SMEM_DYN);

    split_text_kernel<<<(M_TOT * DM) / 8 / 256, 256>>>(text);
    wsplit_kernel<<<dim3(DM / 32, DM / 32), dim3(32, 8)>>>(Wt);
    va_kernel<<<BATCH, DM>>>(ac, Wa, ba, Wv, bv);

    gemm_kernel<<<dim3(DM / BN, M_TOT / BM), 512, SMEM_DYN>>>(bt, out);
}